// round 1
// baseline (speedup 1.0000x reference)
#include <cuda_runtime.h>
#include <cuda_bf16.h>

// ---------------- problem constants ----------------
#define BB    2
#define SS    1024
#define LL    1024
#define DIMQ  2048
#define HH    16
#define KH    128
#define DC    512
#define DCQ   1536
#define RR    64

// ---------------- scratch (device globals, no allocs allowed) ----------------
__device__ float g_qhk [BB * SS * HH * KH];          // [B,S,H*K]          16 MB
__device__ float g_qbig[BB * SS * HH * DCQ];         // [B,S,H,DCQ]       201 MB
__device__ float g_kvr [BB * LL * DC];               // [B,L,DC]            4 MB
__device__ float g_qr  [BB * HH * SS * RR];          // [B,H,S,R]           8 MB
__device__ float g_kr  [BB * HH * LL * RR];          // [B,H,L,R]           8 MB
__device__ float g_sc  [BB * HH * SS * LL];          // [B,H,S,L]         134 MB
__device__ float g_cc  [BB * HH * SS * DC];          // [B,H,S,DC]         67 MB
__device__ float g_ctx [BB * SS * HH * KH];          // [B,S,H*K]          16 MB

// ---------------- generic tiled SGEMM ----------------
// C[m,n] = sum_k A[m,k] * B[k,n]      (TB=false, B row-major [K,N])
// C[m,n] = sum_k A[m,k] * B[n,k]      (TB=true,  B row-major [N,K])
// blockIdx.z = b*numH + h ; per-matrix offsets  base + b*Sb + h*Sh
template<int BM, int BN, bool TB>
__global__ void sgemm_kernel(
    const float* __restrict__ A, const float* __restrict__ Bm, float* __restrict__ C,
    int M, int N, int Kd,
    int lda, int ldb, int ldc,
    long long aSb, long long aSh,
    long long bSb, long long bSh,
    long long cSb, long long cSh,
    int numH)
{
    constexpr int BK = 16;
    constexpr int TX = BN / 8;
    constexpr int TY = BM / 8;
    constexpr int T  = TX * TY;

    __shared__ float As[BK][BM];
    __shared__ float Bs[BK][BN];

    int z  = blockIdx.z;
    int bb = z / numH;
    int hh = z - bb * numH;
    A  += bb * aSb + hh * aSh;
    Bm += bb * bSb + hh * bSh;
    C  += bb * cSb + hh * cSh;

    int tid = threadIdx.x;
    int tx  = tid % TX;
    int ty  = tid / TX;
    int m0  = blockIdx.y * BM;
    int n0  = blockIdx.x * BN;

    float acc[8][8];
    #pragma unroll
    for (int i = 0; i < 8; i++)
        #pragma unroll
        for (int j = 0; j < 8; j++)
            acc[i][j] = 0.f;

    for (int k0 = 0; k0 < Kd; k0 += BK) {
        // --- load A tile (BM x BK), store transposed As[k][m] ---
        #pragma unroll 4
        for (int i = tid; i < BM * BK; i += T) {
            int m = i / BK, k = i - (i / BK) * BK;
            int gm = m0 + m, gk = k0 + k;
            float v = (gm < M && gk < Kd) ? A[(long long)gm * lda + gk] : 0.f;
            As[k][m] = v;
        }
        // --- load B tile ---
        if (!TB) {
            #pragma unroll 4
            for (int i = tid; i < BK * BN; i += T) {
                int k = i / BN, n = i - (i / BN) * BN;
                int gk = k0 + k, gn = n0 + n;
                float v = (gk < Kd && gn < N) ? Bm[(long long)gk * ldb + gn] : 0.f;
                Bs[k][n] = v;
            }
        } else {
            #pragma unroll 4
            for (int i = tid; i < BK * BN; i += T) {
                int n = i / BK, k = i - (i / BK) * BK;
                int gn = n0 + n, gk = k0 + k;
                float v = (gn < N && gk < Kd) ? Bm[(long long)gn * ldb + gk] : 0.f;
                Bs[k][n] = v;
            }
        }
        __syncthreads();

        #pragma unroll
        for (int k = 0; k < BK; k++) {
            float a[8], bv[8];
            #pragma unroll
            for (int i = 0; i < 8; i++) a[i]  = As[k][ty * 8 + i];
            #pragma unroll
            for (int j = 0; j < 8; j++) bv[j] = Bs[k][tx * 8 + j];
            #pragma unroll
            for (int i = 0; i < 8; i++)
                #pragma unroll
                for (int j = 0; j < 8; j++)
                    acc[i][j] += a[i] * bv[j];
        }
        __syncthreads();
    }

    #pragma unroll
    for (int i = 0; i < 8; i++) {
        int gm = m0 + ty * 8 + i;
        if (gm >= M) continue;
        #pragma unroll
        for (int j = 0; j < 8; j++) {
            int gn = n0 + tx * 8 + j;
            if (gn < N) C[(long long)gm * ldc + gn] = acc[i][j];
        }
    }
}

// ---------------- RoPE (repeat_interleave freq tables + rotate-half) ----------------
// out[j]       = x[j]*cos(a1) - x[j+half]*sin(a1)
// out[j+half]  = x[j+half]*cos(a2) + x[j]*sin(a2)
// freq(elem e) = 10000^(-(2*(e>>1))/dim), pos = (row/posDiv) % posMod
__global__ void rope_kernel(const float* __restrict__ in, float* __restrict__ out,
                            long long total, int dim, int half,
                            int posDiv, int posMod)
{
    long long t = (long long)blockIdx.x * blockDim.x + threadIdx.x;
    if (t >= total) return;
    int  j = (int)(t % half);
    long long r = t / half;
    int pos = (int)((r / posDiv) % posMod);

    const float* pin  = in  + r * (long long)dim;
    float*       pout = out + r * (long long)dim;

    float x1 = pin[j];
    float x2 = pin[j + half];

    const float LOG2_1E4 = 13.28771238f;               // log2(10000)
    float inv_dim = 1.0f / (float)dim;
    float e1 = exp2f(-LOG2_1E4 * (float)(2 * (j >> 1))        * inv_dim);
    float e2 = exp2f(-LOG2_1E4 * (float)(2 * (j >> 1) + half) * inv_dim);
    float a1 = (float)pos * e1;
    float a2 = (float)pos * e2;
    float s1, c1, s2, c2;
    sincosf(a1, &s1, &c1);
    sincosf(a2, &s2, &c2);

    pout[j]        = x1 * c1 - x2 * s1;
    pout[j + half] = x2 * c2 + x1 * s2;
}

// ---------------- row softmax (len = 1024) ----------------
__global__ void softmax_kernel(float* __restrict__ x, int len)
{
    long long row = blockIdx.x;
    float* p = x + row * (long long)len;
    int tid = threadIdx.x;
    __shared__ float sh[32];
    int nwarp = blockDim.x >> 5;

    float m = -3.0e38f;
    for (int i = tid; i < len; i += blockDim.x) m = fmaxf(m, p[i]);
    #pragma unroll
    for (int o = 16; o > 0; o >>= 1) m = fmaxf(m, __shfl_xor_sync(0xffffffffu, m, o));
    if ((tid & 31) == 0) sh[tid >> 5] = m;
    __syncthreads();
    if (tid == 0) {
        float mm = sh[0];
        for (int w = 1; w < nwarp; w++) mm = fmaxf(mm, sh[w]);
        sh[0] = mm;
    }
    __syncthreads();
    m = sh[0];
    __syncthreads();

    float s = 0.f;
    for (int i = tid; i < len; i += blockDim.x) {
        float e = __expf(p[i] - m);
        p[i] = e;
        s += e;
    }
    #pragma unroll
    for (int o = 16; o > 0; o >>= 1) s += __shfl_xor_sync(0xffffffffu, s, o);
    if ((tid & 31) == 0) sh[tid >> 5] = s;
    __syncthreads();
    if (tid == 0) {
        float ss = 0.f;
        for (int w = 0; w < nwarp; w++) ss += sh[w];
        sh[0] = ss;
    }
    __syncthreads();
    float inv = 1.f / sh[0];
    for (int i = tid; i < len; i += blockDim.x) p[i] *= inv;
}

// ---------------- launch ----------------
extern "C" void kernel_launch(void* const* d_in, const int* in_sizes, int n_in,
                              void* d_out, int out_size)
{
    const float* hidden  = (const float*)d_in[0];   // [B,S,DIMQ]
    const float* kv_c    = (const float*)d_in[1];   // [B,L,DC]
    const float* Wq      = (const float*)d_in[2];   // [H*K, DIMQ]
    const float* w_kc_q  = (const float*)d_in[3];   // [H,K,DCQ]
    const float* w_kc_kv = (const float*)d_in[4];   // [H,K,DC]
    const float* W_qr    = (const float*)d_in[5];   // [H,DCQ,R]
    const float* W_kr    = (const float*)d_in[6];   // [H,DC,R]
    const float* Wo      = (const float*)d_in[7];   // [DIMQ, H*K]
    float* out = (float*)d_out;

    float *qhk, *qbig, *kvr, *qr, *kr, *sc, *cc, *ctx;
    cudaGetSymbolAddress((void**)&qhk,  g_qhk);
    cudaGetSymbolAddress((void**)&qbig, g_qbig);
    cudaGetSymbolAddress((void**)&kvr,  g_kvr);
    cudaGetSymbolAddress((void**)&qr,   g_qr);
    cudaGetSymbolAddress((void**)&kr,   g_kr);
    cudaGetSymbolAddress((void**)&sc,   g_sc);
    cudaGetSymbolAddress((void**)&cc,   g_cc);
    cudaGetSymbolAddress((void**)&ctx,  g_ctx);

    const int MS = BB * SS;          // 2048

    // 1) q_hk = hidden @ Wq^T    [2048,2048,2048]
    sgemm_kernel<128,128,true><<<dim3(DIMQ/128, MS/128, 1), 256>>>(
        hidden, Wq, qhk, MS, HH*KH, DIMQ,
        DIMQ, DIMQ, HH*KH,
        0,0, 0,0, 0,0, 1);

    // 2) q_big[bs,h,:] = q_hk[bs,h*K:(h+1)*K] @ w_kc_q[h]   [2048,1536,128] x16
    sgemm_kernel<128,128,false><<<dim3(DCQ/128, MS/128, HH), 256>>>(
        qhk, w_kc_q, qbig, MS, DCQ, KH,
        HH*KH, DCQ, HH*DCQ,
        0, KH,                    // A: head column offset
        0, (long long)KH*DCQ,     // B: per-head weight
        0, DCQ,                   // C: head slice of row
        HH);

    // 3) RoPE on q_big (dim 1536, pos = s), in place
    {
        long long total = (long long)BB * SS * HH * (DCQ/2);
        int thr = 256;
        long long blocks = (total + thr - 1) / thr;
        rope_kernel<<<(unsigned)blocks, thr>>>(qbig, qbig, total, DCQ, DCQ/2, HH, SS);
    }

    // 4) RoPE kv_c -> kvr (dim 512, pos = l)
    {
        long long total = (long long)BB * LL * (DC/2);
        int thr = 256;
        long long blocks = (total + thr - 1) / thr;
        rope_kernel<<<(unsigned)blocks, thr>>>(kv_c, kvr, total, DC, DC/2, 1, LL);
    }

    // 5) q_r[b,h] = q_big[b,:,h,:] @ W_qr[h]   [1024,64,1536] x32
    sgemm_kernel<128,64,false><<<dim3(1, SS/128, BB*HH), 128>>>(
        qbig, W_qr, qr, SS, RR, DCQ,
        HH*DCQ, RR, RR,
        (long long)SS*HH*DCQ, DCQ,
        0, (long long)DCQ*RR,
        (long long)HH*SS*RR, (long long)SS*RR,
        HH);

    // 6) k_r[b,h] = kvr[b] @ W_kr[h]           [1024,64,512] x32
    sgemm_kernel<128,64,false><<<dim3(1, LL/128, BB*HH), 128>>>(
        kvr, W_kr, kr, LL, RR, DC,
        DC, RR, RR,
        (long long)LL*DC, 0,
        0, (long long)DC*RR,
        (long long)HH*LL*RR, (long long)LL*RR,
        HH);

    // 7) scores[b,h] = q_r[b,h] @ k_r[b,h]^T   [1024,1024,64] x32
    sgemm_kernel<128,128,true><<<dim3(LL/128, SS/128, BB*HH), 256>>>(
        qr, kr, sc, SS, LL, RR,
        RR, RR, LL,
        (long long)HH*SS*RR, (long long)SS*RR,
        (long long)HH*LL*RR, (long long)LL*RR,
        (long long)HH*SS*LL, (long long)SS*LL,
        HH);

    // 8) softmax rows (B*H*S = 32768, len 1024), in place
    softmax_kernel<<<BB*HH*SS, 256>>>(sc, LL);

    // 9) ctx_c[b,h] = attn[b,h] @ kvr[b]       [1024,512,1024] x32
    sgemm_kernel<128,128,false><<<dim3(DC/128, SS/128, BB*HH), 256>>>(
        sc, kvr, cc, SS, DC, LL,
        LL, DC, DC,
        (long long)HH*SS*LL, (long long)SS*LL,
        (long long)LL*DC, 0,
        (long long)HH*SS*DC, (long long)SS*DC,
        HH);

    // 10) ctx[b,s,h*K+k] = ctx_c[b,h,s,:] @ w_kc_kv[h]^T   [1024,128,512] x32
    sgemm_kernel<128,128,true><<<dim3(1, SS/128, BB*HH), 256>>>(
        cc, w_kc_kv, ctx, SS, KH, DC,
        DC, DC, HH*KH,
        (long long)HH*SS*DC, (long long)SS*DC,
        0, (long long)KH*DC,
        (long long)SS*HH*KH, KH,
        HH);

    // 11) out = ctx @ Wo^T                      [2048,2048,2048]
    sgemm_kernel<128,128,true><<<dim3(DIMQ/128, MS/128, 1), 256>>>(
        ctx, Wo, out, MS, DIMQ, HH*KH,
        HH*KH, HH*KH, DIMQ,
        0,0, 0,0, 0,0, 1);
}

// round 4
// speedup vs baseline: 4.2215x; 4.2215x over previous
#include <cuda_runtime.h>
#include <cuda_bf16.h>
#include <cstdint>

// ---------------- problem constants ----------------
#define BB    2
#define SS    1024
#define LL    1024
#define DIMQ  2048
#define HH    16
#define KH    128
#define DC    512
#define DCQ   1536
#define RR    64

// ---------------- scratch (device globals, no allocs allowed) ----------------
__device__ float g_qhk [BB * SS * HH * KH];
__device__ float g_qbig[BB * SS * HH * DCQ];
__device__ float g_kvr [BB * LL * DC];
__device__ float g_qr  [BB * HH * SS * RR];
__device__ float g_kr  [BB * HH * LL * RR];
__device__ float g_sc  [BB * HH * SS * LL];
__device__ float g_cc  [BB * HH * SS * DC];
__device__ float g_ctx [BB * SS * HH * KH];

// ---------------- helpers ----------------
__device__ __forceinline__ uint32_t smem_u32(const void* p) {
    uint32_t a;
    asm("{ .reg .u64 t; cvta.to.shared.u64 t, %1; cvt.u32.u64 %0, t; }" : "=r"(a) : "l"(p));
    return a;
}
__device__ __forceinline__ void ldsm4(uint32_t a, uint32_t* r) {
    asm volatile("ldmatrix.sync.aligned.m8n8.x4.shared.b16 {%0,%1,%2,%3}, [%4];"
        : "=r"(r[0]), "=r"(r[1]), "=r"(r[2]), "=r"(r[3]) : "r"(a));
}
__device__ __forceinline__ void ldsm4t(uint32_t a, uint32_t* r) {
    asm volatile("ldmatrix.sync.aligned.m8n8.x4.trans.shared.b16 {%0,%1,%2,%3}, [%4];"
        : "=r"(r[0]), "=r"(r[1]), "=r"(r[2]), "=r"(r[3]) : "r"(a));
}
__device__ __forceinline__ void mma_bf16(float* c, const uint32_t* a, const uint32_t* b) {
    asm volatile("mma.sync.aligned.m16n8k16.row.col.f32.bf16.bf16.f32 "
        "{%0,%1,%2,%3},{%4,%5,%6,%7},{%8,%9},{%0,%1,%2,%3};"
        : "+f"(c[0]), "+f"(c[1]), "+f"(c[2]), "+f"(c[3])
        : "r"(a[0]), "r"(a[1]), "r"(a[2]), "r"(a[3]), "r"(b[0]), "r"(b[1]));
}
// hi = truncate-to-bf16, lo = round-to-bf16(x - hi); packed as bf16x2 (low half = first elem)
__device__ __forceinline__ uint32_t pack_hi(float x, float y) {
    return (__float_as_uint(x) >> 16) | (__float_as_uint(y) & 0xffff0000u);
}
__device__ __forceinline__ uint32_t pack_lo(float x, float y) {
    float hx = __uint_as_float(__float_as_uint(x) & 0xffff0000u);
    float hy = __uint_as_float(__float_as_uint(y) & 0xffff0000u);
    __nv_bfloat162 v = __floats2bfloat162_rn(x - hx, y - hy);
    return *reinterpret_cast<uint32_t*>(&v);
}

// ---------------- bf16x3-split MMA GEMM ----------------
// C[m,n] = sum_k A[m,k] * (TB ? B[n,k] : B[k,n]); fp32 in/out, fp32-accurate via 3 bf16 MMAs.
// CTA tile 128 x BN x 32, 8 warps (warp tile 64 x BN/4), double-buffered smem.
template<int BN, bool TB>
__global__ __launch_bounds__(256, 1)
void mma_gemm(const float* __restrict__ A, const float* __restrict__ Bm,
              float* __restrict__ C, int Kd,
              int lda, int ldb, int ldc,
              long long aSb, long long aSh,
              long long bSb, long long bSh,
              long long cSb, long long cSh, int numH)
{
    constexpr int BM    = 128;
    constexpr int BK    = 32;
    constexpr int NF    = BN / 32;            // n8-frags per warp (4 or 2)
    constexpr int AST   = BK + 8;             // 40 bf16 row stride (80B -> conflict-free ldsm)
    constexpr int ATILE = BM * AST;           // bf16 elems per A split
    constexpr int BROWS = TB ? BN : BK;
    constexpr int BST   = TB ? (BK + 8) : (BN + 8);
    constexpr int BTILE = BROWS * BST;
    constexpr int BUFE  = 2 * ATILE + 2 * BTILE;   // elems per buffer
    constexpr int ALD   = (BM * BK) / (4 * 256);   // float4 loads / thread (=4)
    constexpr int BLD   = (BN * BK) / (4 * 256);   // 4 or 2
    constexpr int NP4   = BN / 4;

    extern __shared__ __nv_bfloat16 sm[];

    const int z  = blockIdx.z;
    const int bb = z / numH;
    const int hh = z - bb * numH;
    const int m0 = blockIdx.y * BM;
    const int n0 = blockIdx.x * BN;
    A  += bb * aSb + hh * aSh + (long long)m0 * lda;
    Bm += bb * bSb + hh * bSh;
    C  += bb * cSb + hh * cSh;

    const int tid  = threadIdx.x;
    const int lane = tid & 31;
    const int w    = tid >> 5;
    const int wm   = w & 1;          // warp row (0..1) -> m offset *64
    const int wn   = w >> 1;         // warp col (0..3) -> n offset *NP4

    const uint32_t smb = smem_u32(sm);

    // loader indexing (compile-time friendly)
    const int arow = tid >> 3;          // + 32*r
    const int ak   = (tid & 7) * 4;
    const int brow_f = tid / NP4;       // TB=false: k row, + (256/NP4)*r
    const int bnc_f  = (tid % NP4) * 4;

    // ldmatrix per-lane byte offsets within a split tile
    const uint32_t aFrag = (uint32_t)(((wm * 64 + (lane & 15)) * AST + ((lane >> 4) << 3)) * 2);
    uint32_t bFrag;
    if (TB)
        bFrag = (uint32_t)(((wn * NP4 + (lane & 7) + ((lane >> 4) << 3)) * BST
                            + (((lane >> 3) & 1) << 3)) * 2);
    else
        bFrag = (uint32_t)((((lane & 7) + (((lane >> 3) & 1) << 3)) * BST
                            + wn * NP4 + ((lane >> 4) << 3)) * 2);

    float acc[4][NF][4];
    #pragma unroll
    for (int i = 0; i < 4; i++)
        #pragma unroll
        for (int j = 0; j < NF; j++)
            #pragma unroll
            for (int q = 0; q < 4; q++) acc[i][j][q] = 0.f;

    float4 ra[ALD], rb[BLD];

    auto loadG = [&](int it) {
        const int k0 = it * BK;
        #pragma unroll
        for (int r = 0; r < ALD; r++)
            ra[r] = *(const float4*)&A[(long long)(arow + 32 * r) * lda + k0 + ak];
        if (TB) {
            #pragma unroll
            for (int r = 0; r < BLD; r++)
                rb[r] = *(const float4*)&Bm[(long long)(n0 + arow + 32 * r) * ldb + k0 + ak];
        } else {
            #pragma unroll
            for (int r = 0; r < BLD; r++)
                rb[r] = *(const float4*)&Bm[(long long)(k0 + brow_f + (256 / NP4) * r) * ldb + n0 + bnc_f];
        }
    };

    auto stsT = [&](int it) {
        __nv_bfloat16* buf = sm + (it & 1) * BUFE;
        uint32_t* Ahi = (uint32_t*)buf;
        uint32_t* Alo = (uint32_t*)(buf + ATILE);
        uint32_t* Bhi = (uint32_t*)(buf + 2 * ATILE);
        uint32_t* Blo = (uint32_t*)(buf + 2 * ATILE + BTILE);
        #pragma unroll
        for (int r = 0; r < ALD; r++) {
            int off = ((arow + 32 * r) * AST + ak) >> 1;
            Ahi[off]     = pack_hi(ra[r].x, ra[r].y);
            Ahi[off + 1] = pack_hi(ra[r].z, ra[r].w);
            Alo[off]     = pack_lo(ra[r].x, ra[r].y);
            Alo[off + 1] = pack_lo(ra[r].z, ra[r].w);
        }
        if (TB) {
            #pragma unroll
            for (int r = 0; r < BLD; r++) {
                int off = ((arow + 32 * r) * BST + ak) >> 1;
                Bhi[off]     = pack_hi(rb[r].x, rb[r].y);
                Bhi[off + 1] = pack_hi(rb[r].z, rb[r].w);
                Blo[off]     = pack_lo(rb[r].x, rb[r].y);
                Blo[off + 1] = pack_lo(rb[r].z, rb[r].w);
            }
        } else {
            #pragma unroll
            for (int r = 0; r < BLD; r++) {
                int off = ((brow_f + (256 / NP4) * r) * BST + bnc_f) >> 1;
                Bhi[off]     = pack_hi(rb[r].x, rb[r].y);
                Bhi[off + 1] = pack_hi(rb[r].z, rb[r].w);
                Blo[off]     = pack_lo(rb[r].x, rb[r].y);
                Blo[off + 1] = pack_lo(rb[r].z, rb[r].w);
            }
        }
    };

    auto compute = [&](int it) {
        const uint32_t base = smb + (uint32_t)((it & 1) * BUFE * 2);
        const uint32_t aB = base;
        const uint32_t bB = base + (uint32_t)(2 * ATILE * 2);
        #pragma unroll
        for (int ks = 0; ks < 2; ks++) {
            uint32_t ah[4][4], al[4][4];
            #pragma unroll
            for (int i = 0; i < 4; i++) {
                uint32_t ad = aB + aFrag + (uint32_t)((ks * 16) * 2 + i * (16 * AST * 2));
                ldsm4(ad, ah[i]);
                ldsm4(ad + (uint32_t)(ATILE * 2), al[i]);
            }
            uint32_t bh[NF][2], bl[NF][2];
            #pragma unroll
            for (int jj = 0; jj < NF / 2; jj++) {
                uint32_t bd;
                if (TB) {
                    bd = bB + bFrag + (uint32_t)((ks * 16) * 2 + jj * (16 * BST * 2));
                    ldsm4(bd, &bh[2 * jj][0]);
                    ldsm4(bd + (uint32_t)(BTILE * 2), &bl[2 * jj][0]);
                } else {
                    bd = bB + bFrag + (uint32_t)((ks * 16) * BST * 2 + jj * (16 * 2));
                    ldsm4t(bd, &bh[2 * jj][0]);
                    ldsm4t(bd + (uint32_t)(BTILE * 2), &bl[2 * jj][0]);
                }
            }
            #pragma unroll
            for (int i = 0; i < 4; i++)
                #pragma unroll
                for (int j = 0; j < NF; j++) {
                    mma_bf16(acc[i][j], ah[i], bh[j]);
                    mma_bf16(acc[i][j], al[i], bh[j]);
                    mma_bf16(acc[i][j], ah[i], bl[j]);
                }
        }
    };

    const int nIter = Kd / BK;
    loadG(0);
    stsT(0);
    __syncthreads();
    for (int it = 0; it < nIter; ++it) {
        if (it + 1 < nIter) loadG(it + 1);
        compute(it);
        if (it + 1 < nIter) stsT(it + 1);
        __syncthreads();
    }

    // epilogue
    #pragma unroll
    for (int i = 0; i < 4; i++) {
        int row = m0 + wm * 64 + i * 16 + (lane >> 2);
        #pragma unroll
        for (int j = 0; j < NF; j++) {
            int col = n0 + wn * NP4 + j * 8 + (lane & 3) * 2;
            *(float2*)&C[(long long)row * ldc + col]       = make_float2(acc[i][j][0], acc[i][j][1]);
            *(float2*)&C[(long long)(row + 8) * ldc + col] = make_float2(acc[i][j][2], acc[i][j][3]);
        }
    }
}

// ---------------- RoPE ----------------
__global__ void rope_kernel(const float* __restrict__ in, float* __restrict__ out,
                            long long total, int dim, int half,
                            int posDiv, int posMod)
{
    long long t = (long long)blockIdx.x * blockDim.x + threadIdx.x;
    if (t >= total) return;
    int  j = (int)(t % half);
    long long r = t / half;
    int pos = (int)((r / posDiv) % posMod);

    const float* pin  = in  + r * (long long)dim;
    float*       pout = out + r * (long long)dim;

    float x1 = pin[j];
    float x2 = pin[j + half];

    const float LOG2_1E4 = 13.28771238f;
    float inv_dim = 1.0f / (float)dim;
    float e1 = exp2f(-LOG2_1E4 * (float)(2 * (j >> 1))        * inv_dim);
    float e2 = exp2f(-LOG2_1E4 * (float)(2 * (j >> 1) + half) * inv_dim);
    float a1 = (float)pos * e1;
    float a2 = (float)pos * e2;
    float s1, c1, s2, c2;
    sincosf(a1, &s1, &c1);
    sincosf(a2, &s2, &c2);

    pout[j]        = x1 * c1 - x2 * s1;
    pout[j + half] = x2 * c2 + x1 * s2;
}

// ---------------- single-pass register softmax (len = 1024, 256 threads) ----------------
__global__ void softmax_kernel(float* __restrict__ x)
{
    float4* p = (float4*)(x + (long long)blockIdx.x * 1024);
    int tid  = threadIdx.x;
    int w    = tid >> 5;
    int lane = tid & 31;
    __shared__ float sha[8], shb[8];

    float4 v = p[tid];
    float m = fmaxf(fmaxf(v.x, v.y), fmaxf(v.z, v.w));
    #pragma unroll
    for (int o = 16; o > 0; o >>= 1) m = fmaxf(m, __shfl_xor_sync(0xffffffffu, m, o));
    if (lane == 0) sha[w] = m;
    __syncthreads();
    if (tid == 0) {
        float mm = sha[0];
        #pragma unroll
        for (int i = 1; i < 8; i++) mm = fmaxf(mm, sha[i]);
        sha[0] = mm;
    }
    __syncthreads();
    m = sha[0];

    v.x = __expf(v.x - m);
    v.y = __expf(v.y - m);
    v.z = __expf(v.z - m);
    v.w = __expf(v.w - m);
    float s = v.x + v.y + v.z + v.w;
    #pragma unroll
    for (int o = 16; o > 0; o >>= 1) s += __shfl_xor_sync(0xffffffffu, s, o);
    if (lane == 0) shb[w] = s;
    __syncthreads();
    if (tid == 0) {
        float ss = 0.f;
        #pragma unroll
        for (int i = 0; i < 8; i++) ss += shb[i];
        shb[0] = ss;
    }
    __syncthreads();
    float inv = 1.f / shb[0];
    v.x *= inv; v.y *= inv; v.z *= inv; v.w *= inv;
    p[tid] = v;
}

// ---------------- launch ----------------
static inline void set_smem(const void* fn, int bytes) {
    cudaFuncSetAttribute(fn, cudaFuncAttributeMaxDynamicSharedMemorySize, bytes);
}

extern "C" void kernel_launch(void* const* d_in, const int* in_sizes, int n_in,
                              void* d_out, int out_size)
{
    const float* hidden  = (const float*)d_in[0];
    const float* kv_c    = (const float*)d_in[1];
    const float* Wq      = (const float*)d_in[2];
    const float* w_kc_q  = (const float*)d_in[3];
    const float* w_kc_kv = (const float*)d_in[4];
    const float* W_qr    = (const float*)d_in[5];
    const float* W_kr    = (const float*)d_in[6];
    const float* Wo      = (const float*)d_in[7];
    float* out = (float*)d_out;

    float *qhk, *qbig, *kvr, *qr, *kr, *sc, *cc, *ctx;
    cudaGetSymbolAddress((void**)&qhk,  g_qhk);
    cudaGetSymbolAddress((void**)&qbig, g_qbig);
    cudaGetSymbolAddress((void**)&kvr,  g_kvr);
    cudaGetSymbolAddress((void**)&qr,   g_qr);
    cudaGetSymbolAddress((void**)&kr,   g_kr);
    cudaGetSymbolAddress((void**)&sc,   g_sc);
    cudaGetSymbolAddress((void**)&cc,   g_cc);
    cudaGetSymbolAddress((void**)&ctx,  g_ctx);

    const int MS = BB * SS;
    // dynamic smem: 2 buffers x (2*A + 2*B) bf16 tiles
    const int SM_T128 = 81920;  // TB=true,  BN=128
    const int SM_F128 = 75776;  // TB=false, BN=128
    const int SM_F64  = 59392;  // TB=false, BN=64

    set_smem((const void*)mma_gemm<128, true>,  SM_T128);
    set_smem((const void*)mma_gemm<128, false>, SM_F128);
    set_smem((const void*)mma_gemm<64,  false>, SM_F64);

    // 1) q_hk = hidden @ Wq^T    [2048,2048,2048]
    mma_gemm<128, true><<<dim3(DIMQ/128, MS/128, 1), 256, SM_T128>>>(
        hidden, Wq, qhk, DIMQ,
        DIMQ, DIMQ, HH*KH,
        0, 0, 0, 0, 0, 0, 1);

    // 2) q_big[bs,h,:] = q_hk[bs, h*K:(h+1)*K] @ w_kc_q[h]   [2048,1536,128] x16
    mma_gemm<128, false><<<dim3(DCQ/128, MS/128, HH), 256, SM_F128>>>(
        qhk, w_kc_q, qbig, KH,
        HH*KH, DCQ, HH*DCQ,
        0, KH,
        0, (long long)KH*DCQ,
        0, DCQ,
        HH);

    // 3) RoPE on q_big (dim 1536, pos = s)
    {
        long long total = (long long)BB * SS * HH * (DCQ/2);
        rope_kernel<<<(unsigned)((total + 255) / 256), 256>>>(qbig, qbig, total, DCQ, DCQ/2, HH, SS);
    }
    // 4) RoPE kv_c -> kvr (dim 512, pos = l)
    {
        long long total = (long long)BB * LL * (DC/2);
        rope_kernel<<<(unsigned)((total + 255) / 256), 256>>>(kv_c, kvr, total, DC, DC/2, 1, LL);
    }

    // 5) q_r[b,h] = q_big[b,:,h,:] @ W_qr[h]   [1024,64,1536] x32
    mma_gemm<64, false><<<dim3(1, SS/128, BB*HH), 256, SM_F64>>>(
        qbig, W_qr, qr, DCQ,
        HH*DCQ, RR, RR,
        (long long)SS*HH*DCQ, DCQ,
        0, (long long)DCQ*RR,
        (long long)HH*SS*RR, (long long)SS*RR,
        HH);

    // 6) k_r[b,h] = kvr[b] @ W_kr[h]           [1024,64,512] x32
    mma_gemm<64, false><<<dim3(1, LL/128, BB*HH), 256, SM_F64>>>(
        kvr, W_kr, kr, DC,
        DC, RR, RR,
        (long long)LL*DC, 0,
        0, (long long)DC*RR,
        (long long)HH*LL*RR, (long long)LL*RR,
        HH);

    // 7) scores[b,h] = q_r[b,h] @ k_r[b,h]^T   [1024,1024,64] x32
    mma_gemm<128, true><<<dim3(LL/128, SS/128, BB*HH), 256, SM_T128>>>(
        qr, kr, sc, RR,
        RR, RR, LL,
        (long long)HH*SS*RR, (long long)SS*RR,
        (long long)HH*LL*RR, (long long)LL*RR,
        (long long)HH*SS*LL, (long long)SS*LL,
        HH);

    // 8) softmax rows (B*H*S = 32768, len 1024)
    softmax_kernel<<<BB*HH*SS, 256>>>(sc);

    // 9) ctx_c[b,h] = attn[b,h] @ kvr[b]       [1024,512,1024] x32
    mma_gemm<128, false><<<dim3(DC/128, SS/128, BB*HH), 256, SM_F128>>>(
        sc, kvr, cc, LL,
        LL, DC, DC,
        (long long)HH*SS*LL, (long long)SS*LL,
        (long long)LL*DC, 0,
        (long long)HH*SS*DC, (long long)SS*DC,
        HH);

    // 10) ctx[b,s,h*K+k] = ctx_c[b,h,s,:] @ w_kc_kv[h]^T   [1024,128,512] x32
    mma_gemm<128, true><<<dim3(1, SS/128, BB*HH), 256, SM_T128>>>(
        cc, w_kc_kv, ctx, DC,
        DC, DC, HH*KH,
        (long long)HH*SS*DC, (long long)SS*DC,
        0, (long long)KH*DC,
        (long long)SS*HH*KH, KH,
        HH);

    // 11) out = ctx @ Wo^T                      [2048,2048,2048]
    mma_gemm<128, true><<<dim3(DIMQ/128, MS/128, 1), 256, SM_T128>>>(
        ctx, Wo, out, HH*KH,
        HH*KH, HH*KH, DIMQ,
        0, 0, 0, 0, 0, 0, 1);
}

// round 5
// speedup vs baseline: 4.3652x; 1.0340x over previous
#include <cuda_runtime.h>
#include <cuda_bf16.h>
#include <cstdint>

// ---------------- problem constants ----------------
#define BB    2
#define SS    1024
#define LL    1024
#define DIMQ  2048
#define HH    16
#define KH    128
#define DC    512
#define DCQ   1536
#define RR    64

typedef __nv_bfloat16 bf16;

// ---------------- scratch (device globals, no allocs allowed) ----------------
#define DEVARR(name, n) __device__ __align__(256) bf16 name##_h[n]; __device__ __align__(256) bf16 name##_l[n];
DEVARR(s_hid,   BB * SS * DIMQ)
DEVARR(s_wq,    HH * KH * DIMQ)
DEVARR(s_wkcq,  HH * KH * DCQ)
DEVARR(s_wkckv, HH * KH * DC)
DEVARR(s_wqr,   HH * DCQ * RR)
DEVARR(s_wkr,   HH * DC * RR)
DEVARR(s_wo,    DIMQ * HH * KH)
DEVARR(s_qhk,   BB * SS * HH * KH)
DEVARR(s_qbig,  BB * SS * HH * DCQ)
DEVARR(s_kvr,   BB * LL * DC)
DEVARR(s_qr,    BB * HH * SS * RR)
DEVARR(s_kr,    BB * HH * LL * RR)
DEVARR(s_at,    BB * HH * SS * LL)
DEVARR(s_cc,    BB * HH * SS * DC)
DEVARR(s_ctx,   BB * SS * HH * KH)
__device__ __align__(256) float g_qbig[BB * SS * HH * DCQ];
__device__ __align__(256) float g_sc  [BB * HH * SS * LL];

// ---------------- helpers ----------------
__device__ __forceinline__ uint32_t smem_u32(const void* p) {
    uint32_t a;
    asm("{ .reg .u64 t; cvta.to.shared.u64 t, %1; cvt.u32.u64 %0, t; }" : "=r"(a) : "l"(p));
    return a;
}
__device__ __forceinline__ void ldsm4(uint32_t a, uint32_t* r) {
    asm volatile("ldmatrix.sync.aligned.m8n8.x4.shared.b16 {%0,%1,%2,%3}, [%4];"
        : "=r"(r[0]), "=r"(r[1]), "=r"(r[2]), "=r"(r[3]) : "r"(a));
}
__device__ __forceinline__ void ldsm4t(uint32_t a, uint32_t* r) {
    asm volatile("ldmatrix.sync.aligned.m8n8.x4.trans.shared.b16 {%0,%1,%2,%3}, [%4];"
        : "=r"(r[0]), "=r"(r[1]), "=r"(r[2]), "=r"(r[3]) : "r"(a));
}
__device__ __forceinline__ void mma_bf16(float* c, const uint32_t* a, const uint32_t* b) {
    asm volatile("mma.sync.aligned.m16n8k16.row.col.f32.bf16.bf16.f32 "
        "{%0,%1,%2,%3},{%4,%5,%6,%7},{%8,%9},{%0,%1,%2,%3};"
        : "+f"(c[0]), "+f"(c[1]), "+f"(c[2]), "+f"(c[3])
        : "r"(a[0]), "r"(a[1]), "r"(a[2]), "r"(a[3]), "r"(b[0]), "r"(b[1]));
}
__device__ __forceinline__ uint32_t pack_hi(float x, float y) {
    return (__float_as_uint(x) >> 16) | (__float_as_uint(y) & 0xffff0000u);
}
__device__ __forceinline__ uint32_t pack_lo(float x, float y) {
    float hx = __uint_as_float(__float_as_uint(x) & 0xffff0000u);
    float hy = __uint_as_float(__float_as_uint(y) & 0xffff0000u);
    __nv_bfloat162 v = __floats2bfloat162_rn(x - hx, y - hy);
    return *reinterpret_cast<uint32_t*>(&v);
}
__device__ __forceinline__ void cpa16(uint32_t s, const void* g) {
    asm volatile("cp.async.ca.shared.global [%0], [%1], 16;" :: "r"(s), "l"(g));
}
#define CP_COMMIT() asm volatile("cp.async.commit_group;" ::: "memory")
#define CP_WAIT(n)  asm volatile("cp.async.wait_group %0;" :: "n"(n) : "memory")

// ---------------- bf16x3-split MMA GEMM (pre-split operands, cp.async pipeline) ----------------
// C = A * (TB ? B^T : B); A = Ah+Al, B = Bh+Bl; 3 MMAs: AhBh + AlBh + AhBl.
// CTA 128 x BN x 32, 8 warps, double-buffered smem.
template<int BN, bool TB, bool SPLIT>
__global__ __launch_bounds__(256, 1)
void mma_gemm(const bf16* __restrict__ Ah, const bf16* __restrict__ Al,
              const bf16* __restrict__ Bh, const bf16* __restrict__ Bl,
              float* __restrict__ Cf, bf16* __restrict__ Ch, bf16* __restrict__ Cl,
              int Kd, int lda, int ldb, int ldc,
              long long aSb, long long aSh,
              long long bSb, long long bSh,
              long long cSb, long long cSh, int numH)
{
    constexpr int BM    = 128;
    constexpr int BK    = 32;
    constexpr int NF    = BN / 32;
    constexpr int AST   = BK + 8;                 // 40
    constexpr int ATILE = BM * AST;               // 5120
    constexpr int BROWS = TB ? BN : BK;
    constexpr int BST   = TB ? (BK + 8) : (BN + 8);
    constexpr int BTILE = BROWS * BST;
    constexpr int BUFE  = 2 * ATILE + 2 * BTILE;
    constexpr int NP4   = BN / 4;
    constexpr int NCHB  = TB ? (BN * 4) : (32 * (BN / 8));  // 16B chunks per B array

    extern __shared__ bf16 sm[];

    const int z  = blockIdx.z;
    const int bb = z / numH;
    const int hh = z - bb * numH;
    const int m0 = blockIdx.y * BM;
    const int n0 = blockIdx.x * BN;
    Ah += bb * aSb + hh * aSh + (long long)m0 * lda;
    Al += bb * aSb + hh * aSh + (long long)m0 * lda;
    Bh += bb * bSb + hh * bSh;
    Bl += bb * bSb + hh * bSh;

    const int tid  = threadIdx.x;
    const int lane = tid & 31;
    const int w    = tid >> 5;
    const int wm   = w & 1;
    const int wn   = w >> 1;

    const uint32_t smb = smem_u32(sm);

    // ldmatrix per-lane byte offsets
    const uint32_t aFrag = (uint32_t)(((wm * 64 + (lane & 15)) * AST + ((lane >> 4) << 3)) * 2);
    uint32_t bFrag;
    if (TB)
        bFrag = (uint32_t)(((wn * NP4 + (lane & 7) + ((lane >> 4) << 3)) * BST
                            + (((lane >> 3) & 1) << 3)) * 2);
    else
        bFrag = (uint32_t)((((lane & 7) + (((lane >> 3) & 1) << 3)) * BST
                            + wn * NP4 + ((lane >> 4) << 3)) * 2);

    float acc[4][NF][4];
    #pragma unroll
    for (int i = 0; i < 4; i++)
        #pragma unroll
        for (int j = 0; j < NF; j++)
            #pragma unroll
            for (int q = 0; q < 4; q++) acc[i][j][q] = 0.f;

    auto issueLoads = [&](int it) {
        const int k0 = it * BK;
        const uint32_t base = smb + (uint32_t)((it & 1) * BUFE * 2);
        // A hi/lo: 512 chunks each
        #pragma unroll
        for (int r = 0; r < 2; r++) {
            int c   = tid + r * 256;
            int row = c >> 2;
            int ch  = c & 3;
            uint32_t so = base + (uint32_t)((row * AST + ch * 8) * 2);
            const long long go = (long long)row * lda + k0 + ch * 8;
            cpa16(so,                          Ah + go);
            cpa16(so + (uint32_t)(ATILE * 2),  Al + go);
        }
        // B hi/lo
        const uint32_t bBase = base + (uint32_t)(2 * ATILE * 2);
        #pragma unroll
        for (int r = 0; r < NCHB / 256; r++) {
            int c = tid + r * 256;
            int row, ch;
            long long go;
            if (TB) {
                row = c >> 2; ch = c & 3;
                go = (long long)(n0 + row) * ldb + k0 + ch * 8;
            } else {
                row = c / (BN / 8); ch = c % (BN / 8);
                go = (long long)(k0 + row) * ldb + n0 + ch * 8;
            }
            uint32_t so = bBase + (uint32_t)((row * BST + ch * 8) * 2);
            cpa16(so,                          Bh + go);
            cpa16(so + (uint32_t)(BTILE * 2),  Bl + go);
        }
    };

    auto compute = [&](int it) {
        const uint32_t base = smb + (uint32_t)((it & 1) * BUFE * 2);
        const uint32_t aB = base;
        const uint32_t bB = base + (uint32_t)(2 * ATILE * 2);
        #pragma unroll
        for (int ks = 0; ks < 2; ks++) {
            uint32_t ah[4][4], al[4][4];
            #pragma unroll
            for (int i = 0; i < 4; i++) {
                uint32_t ad = aB + aFrag + (uint32_t)((ks * 16) * 2 + i * (16 * AST * 2));
                ldsm4(ad, ah[i]);
                ldsm4(ad + (uint32_t)(ATILE * 2), al[i]);
            }
            uint32_t bh[NF][2], bl[NF][2];
            #pragma unroll
            for (int jj = 0; jj < NF / 2; jj++) {
                uint32_t bd;
                if (TB) {
                    bd = bB + bFrag + (uint32_t)((ks * 16) * 2 + jj * (16 * BST * 2));
                    ldsm4(bd, &bh[2 * jj][0]);
                    ldsm4(bd + (uint32_t)(BTILE * 2), &bl[2 * jj][0]);
                } else {
                    bd = bB + bFrag + (uint32_t)((ks * 16) * BST * 2 + jj * (16 * 2));
                    ldsm4t(bd, &bh[2 * jj][0]);
                    ldsm4t(bd + (uint32_t)(BTILE * 2), &bl[2 * jj][0]);
                }
            }
            #pragma unroll
            for (int i = 0; i < 4; i++)
                #pragma unroll
                for (int j = 0; j < NF; j++) {
                    mma_bf16(acc[i][j], ah[i], bh[j]);
                    mma_bf16(acc[i][j], al[i], bh[j]);
                    mma_bf16(acc[i][j], ah[i], bl[j]);
                }
        }
    };

    const int nIter = Kd / BK;
    issueLoads(0);
    CP_COMMIT();
    for (int it = 0; it < nIter; ++it) {
        if (it + 1 < nIter) {
            issueLoads(it + 1);
            CP_COMMIT();
            CP_WAIT(1);
        } else {
            CP_WAIT(0);
        }
        __syncthreads();
        compute(it);
        __syncthreads();
    }

    // ---- epilogue ----
    const long long cOff = bb * cSb + hh * cSh;
    #pragma unroll
    for (int i = 0; i < 4; i++) {
        const int row = m0 + wm * 64 + i * 16 + (lane >> 2);
        #pragma unroll
        for (int j = 0; j < NF; j++) {
            const int col = n0 + wn * NP4 + j * 8 + (lane & 3) * 2;
            const long long o0 = cOff + (long long)row * ldc + col;
            const long long o1 = cOff + (long long)(row + 8) * ldc + col;
            if (SPLIT) {
                *(uint32_t*)&Ch[o0] = pack_hi(acc[i][j][0], acc[i][j][1]);
                *(uint32_t*)&Cl[o0] = pack_lo(acc[i][j][0], acc[i][j][1]);
                *(uint32_t*)&Ch[o1] = pack_hi(acc[i][j][2], acc[i][j][3]);
                *(uint32_t*)&Cl[o1] = pack_lo(acc[i][j][2], acc[i][j][3]);
            } else {
                *(float2*)&Cf[o0] = make_float2(acc[i][j][0], acc[i][j][1]);
                *(float2*)&Cf[o1] = make_float2(acc[i][j][2], acc[i][j][3]);
            }
        }
    }
}

// ---------------- fp32 -> hi/lo bf16 split ----------------
__global__ void split_kernel(const float4* __restrict__ in,
                             uint32_t* __restrict__ hi, uint32_t* __restrict__ lo, int n4)
{
    int i = blockIdx.x * blockDim.x + threadIdx.x;
    if (i >= n4) return;
    float4 v = in[i];
    hi[2 * i]     = pack_hi(v.x, v.y);
    hi[2 * i + 1] = pack_hi(v.z, v.w);
    lo[2 * i]     = pack_lo(v.x, v.y);
    lo[2 * i + 1] = pack_lo(v.z, v.w);
}

// ---------------- RoPE fused with split ----------------
// element pair (j, j+1) shares angle (repeat_interleave layout); rotate-half partner at +half
__global__ void rope_split_kernel(const float* __restrict__ in,
                                  uint32_t* __restrict__ oh, uint32_t* __restrict__ ol,
                                  long long total, int dim, int half,
                                  int posDiv, int posMod)
{
    long long t = (long long)blockIdx.x * blockDim.x + threadIdx.x;
    if (t >= total) return;
    const int q  = half >> 1;
    const int j  = (int)(t % q) * 2;
    const long long r = t / q;
    const int pos = (int)((r / posDiv) % posMod);

    const float* p = in + r * (long long)dim;
    float x1a = p[j],        x1b = p[j + 1];
    float x2a = p[j + half], x2b = p[j + half + 1];

    const float LOG2_1E4 = 13.28771238f;
    float inv_dim = 1.0f / (float)dim;
    float e1 = exp2f(-LOG2_1E4 * (float)j          * inv_dim);
    float e2 = exp2f(-LOG2_1E4 * (float)(j + half) * inv_dim);
    float s1, c1, s2, c2;
    sincosf((float)pos * e1, &s1, &c1);
    sincosf((float)pos * e2, &s2, &c2);

    float oa = x1a * c1 - x2a * s1, ob = x1b * c1 - x2b * s1;
    float pa = x2a * c2 + x1a * s2, pb = x2b * c2 + x1b * s2;

    long long b0 = (r * dim + j) >> 1;
    long long b1 = (r * dim + j + half) >> 1;
    oh[b0] = pack_hi(oa, ob);  ol[b0] = pack_lo(oa, ob);
    oh[b1] = pack_hi(pa, pb);  ol[b1] = pack_lo(pa, pb);
}

// ---------------- softmax (len 1024) fused with split ----------------
__global__ void softmax_kernel(const float* __restrict__ x,
                               uint32_t* __restrict__ oh, uint32_t* __restrict__ ol)
{
    const float4* p = (const float4*)(x + (long long)blockIdx.x * 1024);
    int tid  = threadIdx.x;
    int w    = tid >> 5;
    int lane = tid & 31;
    __shared__ float sha[8], shb[8];

    float4 v = p[tid];
    float m = fmaxf(fmaxf(v.x, v.y), fmaxf(v.z, v.w));
    #pragma unroll
    for (int o = 16; o > 0; o >>= 1) m = fmaxf(m, __shfl_xor_sync(0xffffffffu, m, o));
    if (lane == 0) sha[w] = m;
    __syncthreads();
    if (tid == 0) {
        float mm = sha[0];
        #pragma unroll
        for (int i = 1; i < 8; i++) mm = fmaxf(mm, sha[i]);
        sha[0] = mm;
    }
    __syncthreads();
    m = sha[0];

    v.x = __expf(v.x - m);
    v.y = __expf(v.y - m);
    v.z = __expf(v.z - m);
    v.w = __expf(v.w - m);
    float s = v.x + v.y + v.z + v.w;
    #pragma unroll
    for (int o = 16; o > 0; o >>= 1) s += __shfl_xor_sync(0xffffffffu, s, o);
    if (lane == 0) shb[w] = s;
    __syncthreads();
    if (tid == 0) {
        float ss = 0.f;
        #pragma unroll
        for (int i = 0; i < 8; i++) ss += shb[i];
        shb[0] = ss;
    }
    __syncthreads();
    float inv = 1.f / shb[0];
    v.x *= inv; v.y *= inv; v.z *= inv; v.w *= inv;

    long long base = ((long long)blockIdx.x * 1024 + tid * 4) >> 1;
    oh[base]     = pack_hi(v.x, v.y);
    oh[base + 1] = pack_hi(v.z, v.w);
    ol[base]     = pack_lo(v.x, v.y);
    ol[base + 1] = pack_lo(v.z, v.w);
}

// ---------------- launch ----------------
static inline void set_smem(const void* fn, int bytes) {
    cudaFuncSetAttribute(fn, cudaFuncAttributeMaxDynamicSharedMemorySize, bytes);
}

#define GETSYM(var, sym) cudaGetSymbolAddress((void**)&var, sym)

extern "C" void kernel_launch(void* const* d_in, const int* in_sizes, int n_in,
                              void* d_out, int out_size)
{
    const float* hidden  = (const float*)d_in[0];
    const float* kv_c    = (const float*)d_in[1];
    const float* Wq      = (const float*)d_in[2];
    const float* w_kc_q  = (const float*)d_in[3];
    const float* w_kc_kv = (const float*)d_in[4];
    const float* W_qr    = (const float*)d_in[5];
    const float* W_kr    = (const float*)d_in[6];
    const float* Wo      = (const float*)d_in[7];
    float* out = (float*)d_out;

    bf16 *hidh, *hidl, *wqh, *wql, *wkcqh, *wkcql, *wkckvh, *wkckvl;
    bf16 *wqrh, *wqrl, *wkrh, *wkrl, *woh, *wol;
    bf16 *qhkh, *qhkl, *qbh, *qbl, *kvrh, *kvrl, *qrh, *qrl, *krh, *krl;
    bf16 *ath, *atl, *cch, *ccl, *ctxh, *ctxl;
    float *qbigf, *scf;

    GETSYM(hidh, s_hid_h);     GETSYM(hidl, s_hid_l);
    GETSYM(wqh, s_wq_h);       GETSYM(wql, s_wq_l);
    GETSYM(wkcqh, s_wkcq_h);   GETSYM(wkcql, s_wkcq_l);
    GETSYM(wkckvh, s_wkckv_h); GETSYM(wkckvl, s_wkckv_l);
    GETSYM(wqrh, s_wqr_h);     GETSYM(wqrl, s_wqr_l);
    GETSYM(wkrh, s_wkr_h);     GETSYM(wkrl, s_wkr_l);
    GETSYM(woh, s_wo_h);       GETSYM(wol, s_wo_l);
    GETSYM(qhkh, s_qhk_h);     GETSYM(qhkl, s_qhk_l);
    GETSYM(qbh, s_qbig_h);     GETSYM(qbl, s_qbig_l);
    GETSYM(kvrh, s_kvr_h);     GETSYM(kvrl, s_kvr_l);
    GETSYM(qrh, s_qr_h);       GETSYM(qrl, s_qr_l);
    GETSYM(krh, s_kr_h);       GETSYM(krl, s_kr_l);
    GETSYM(ath, s_at_h);       GETSYM(atl, s_at_l);
    GETSYM(cch, s_cc_h);       GETSYM(ccl, s_cc_l);
    GETSYM(ctxh, s_ctx_h);     GETSYM(ctxl, s_ctx_l);
    GETSYM(qbigf, g_qbig);     GETSYM(scf, g_sc);

    const int MS = BB * SS;
    const int SM_T128 = 81920;
    const int SM_F128 = 75776;
    const int SM_F64  = 59392;

    set_smem((const void*)mma_gemm<128, true,  true>,  SM_T128);
    set_smem((const void*)mma_gemm<128, true,  false>, SM_T128);
    set_smem((const void*)mma_gemm<128, false, true>,  SM_F128);
    set_smem((const void*)mma_gemm<128, false, false>, SM_F128);
    set_smem((const void*)mma_gemm<64,  false, true>,  SM_F64);

    // ---- operand splits ----
    auto split = [&](const float* src, bf16* h, bf16* l, int elems) {
        split_kernel<<<elems / 1024, 256>>>((const float4*)src, (uint32_t*)h, (uint32_t*)l, elems / 4);
    };
    split(hidden,  hidh,   hidl,   BB * SS * DIMQ);
    split(Wq,      wqh,    wql,    HH * KH * DIMQ);
    split(w_kc_q,  wkcqh,  wkcql,  HH * KH * DCQ);
    split(w_kc_kv, wkckvh, wkckvl, HH * KH * DC);
    split(W_qr,    wqrh,   wqrl,   HH * DCQ * RR);
    split(W_kr,    wkrh,   wkrl,   HH * DC * RR);
    split(Wo,      woh,    wol,    DIMQ * HH * KH);

    // 1) q_hk = hidden @ Wq^T     -> split out
    mma_gemm<128, true, true><<<dim3(DIMQ/128, MS/128, 1), 256, SM_T128>>>(
        hidh, hidl, wqh, wql, nullptr, qhkh, qhkl,
        DIMQ, DIMQ, DIMQ, HH*KH,
        0, 0, 0, 0, 0, 0, 1);

    // 2) q_big = q_hk[h-slice] @ w_kc_q[h]  -> fp32 (pre-RoPE)
    mma_gemm<128, false, false><<<dim3(DCQ/128, MS/128, HH), 256, SM_F128>>>(
        qhkh, qhkl, wkcqh, wkcql, qbigf, nullptr, nullptr,
        KH, HH*KH, DCQ, HH*DCQ,
        0, KH,
        0, (long long)KH*DCQ,
        0, DCQ,
        HH);

    // 3) RoPE+split q_big
    {
        long long total = (long long)BB * SS * HH * (DCQ / 4);
        rope_split_kernel<<<(unsigned)((total + 255) / 256), 256>>>(
            qbigf, (uint32_t*)qbh, (uint32_t*)qbl, total, DCQ, DCQ/2, HH, SS);
    }
    // 4) RoPE+split kv_c -> kvr
    {
        long long total = (long long)BB * LL * (DC / 4);
        rope_split_kernel<<<(unsigned)((total + 255) / 256), 256>>>(
            kv_c, (uint32_t*)kvrh, (uint32_t*)kvrl, total, DC, DC/2, 1, LL);
    }

    // 5) q_r = q_big[b,:,h,:] @ W_qr[h]  -> split out
    mma_gemm<64, false, true><<<dim3(1, SS/128, BB*HH), 256, SM_F64>>>(
        qbh, qbl, wqrh, wqrl, nullptr, qrh, qrl,
        DCQ, HH*DCQ, RR, RR,
        (long long)SS*HH*DCQ, DCQ,
        0, (long long)DCQ*RR,
        (long long)HH*SS*RR, (long long)SS*RR,
        HH);

    // 6) k_r = kvr[b] @ W_kr[h]  -> split out
    mma_gemm<64, false, true><<<dim3(1, LL/128, BB*HH), 256, SM_F64>>>(
        kvrh, kvrl, wkrh, wkrl, nullptr, krh, krl,
        DC, DC, RR, RR,
        (long long)LL*DC, 0,
        0, (long long)DC*RR,
        (long long)HH*LL*RR, (long long)LL*RR,
        HH);

    // 7) scores = q_r @ k_r^T  -> fp32 (pre-softmax)
    mma_gemm<128, true, false><<<dim3(LL/128, SS/128, BB*HH), 256, SM_T128>>>(
        qrh, qrl, krh, krl, scf, nullptr, nullptr,
        RR, RR, RR, LL,
        (long long)HH*SS*RR, (long long)SS*RR,
        (long long)HH*LL*RR, (long long)LL*RR,
        (long long)HH*SS*LL, (long long)SS*LL,
        HH);

    // 8) softmax + split
    softmax_kernel<<<BB*HH*SS, 256>>>(scf, (uint32_t*)ath, (uint32_t*)atl);

    // 9) ctx_c = attn @ kvr  -> split out
    mma_gemm<128, false, true><<<dim3(DC/128, SS/128, BB*HH), 256, SM_F128>>>(
        ath, atl, kvrh, kvrl, nullptr, cch, ccl,
        LL, LL, DC, DC,
        (long long)HH*SS*LL, (long long)SS*LL,
        (long long)LL*DC, 0,
        (long long)HH*SS*DC, (long long)SS*DC,
        HH);

    // 10) ctx = ctx_c @ w_kc_kv^T  -> split out
    mma_gemm<128, true, true><<<dim3(1, SS/128, BB*HH), 256, SM_T128>>>(
        cch, ccl, wkckvh, wkckvl, nullptr, ctxh, ctxl,
        DC, DC, DC, HH*KH,
        (long long)HH*SS*DC, (long long)SS*DC,
        0, (long long)KH*DC,
        (long long)SS*HH*KH, KH,
        HH);

    // 11) out = ctx @ Wo^T  -> fp32 final
    mma_gemm<128, true, false><<<dim3(DIMQ/128, MS/128, 1), 256, SM_T128>>>(
        ctxh, ctxl, woh, wol, out, nullptr, nullptr,
        HH*KH, HH*KH, HH*KH, DIMQ,
        0, 0, 0, 0, 0, 0, 1);
}

// round 6
// speedup vs baseline: 5.5813x; 1.2786x over previous
#include <cuda_runtime.h>
#include <cuda_bf16.h>
#include <cstdint>

// ---------------- problem constants ----------------
#define BB    2
#define SS    1024
#define LL    1024
#define DIMQ  2048
#define HH    16
#define KH    128
#define DC    512
#define DCQ   1536
#define RR    64

typedef __nv_bfloat16 bf16;

// ---------------- scratch (device globals, no allocs allowed) ----------------
#define DEVARR(name, n) __device__ __align__(256) bf16 name##_h[n]; __device__ __align__(256) bf16 name##_l[n];
DEVARR(s_hid,   BB * SS * DIMQ)
DEVARR(s_wq,    HH * KH * DIMQ)
DEVARR(s_wkcq,  HH * KH * DCQ)
DEVARR(s_wkckv, HH * KH * DC)
DEVARR(s_wqr,   HH * DCQ * RR)
DEVARR(s_wkr,   HH * DC * RR)
DEVARR(s_wo,    DIMQ * HH * KH)
DEVARR(s_qhk,   BB * SS * HH * KH)
DEVARR(s_qbig,  BB * SS * HH * DCQ)
DEVARR(s_kvr,   BB * LL * DC)
DEVARR(s_qr,    BB * HH * SS * RR)
DEVARR(s_kr,    BB * HH * LL * RR)
DEVARR(s_at,    BB * HH * SS * LL)
DEVARR(s_v,     BB * HH * LL * KH)
DEVARR(s_ctx,   BB * SS * HH * KH)
__device__ __align__(256) float g_qbig[BB * SS * HH * DCQ];
__device__ __align__(256) float g_sc  [BB * HH * SS * LL];

// ---------------- helpers ----------------
__device__ __forceinline__ uint32_t smem_u32(const void* p) {
    uint32_t a;
    asm("{ .reg .u64 t; cvta.to.shared.u64 t, %1; cvt.u32.u64 %0, t; }" : "=r"(a) : "l"(p));
    return a;
}
__device__ __forceinline__ void ldsm4(uint32_t a, uint32_t* r) {
    asm volatile("ldmatrix.sync.aligned.m8n8.x4.shared.b16 {%0,%1,%2,%3}, [%4];"
        : "=r"(r[0]), "=r"(r[1]), "=r"(r[2]), "=r"(r[3]) : "r"(a));
}
__device__ __forceinline__ void ldsm4t(uint32_t a, uint32_t* r) {
    asm volatile("ldmatrix.sync.aligned.m8n8.x4.trans.shared.b16 {%0,%1,%2,%3}, [%4];"
        : "=r"(r[0]), "=r"(r[1]), "=r"(r[2]), "=r"(r[3]) : "r"(a));
}
__device__ __forceinline__ void mma_bf16(float* c, const uint32_t* a, const uint32_t* b) {
    asm volatile("mma.sync.aligned.m16n8k16.row.col.f32.bf16.bf16.f32 "
        "{%0,%1,%2,%3},{%4,%5,%6,%7},{%8,%9},{%0,%1,%2,%3};"
        : "+f"(c[0]), "+f"(c[1]), "+f"(c[2]), "+f"(c[3])
        : "r"(a[0]), "r"(a[1]), "r"(a[2]), "r"(a[3]), "r"(b[0]), "r"(b[1]));
}
__device__ __forceinline__ uint32_t pack_hi(float x, float y) {
    return (__float_as_uint(x) >> 16) | (__float_as_uint(y) & 0xffff0000u);
}
__device__ __forceinline__ uint32_t pack_lo(float x, float y) {
    float hx = __uint_as_float(__float_as_uint(x) & 0xffff0000u);
    float hy = __uint_as_float(__float_as_uint(y) & 0xffff0000u);
    __nv_bfloat162 v = __floats2bfloat162_rn(x - hx, y - hy);
    return *reinterpret_cast<uint32_t*>(&v);
}
__device__ __forceinline__ void cpa16(uint32_t s, const void* g) {
    asm volatile("cp.async.ca.shared.global [%0], [%1], 16;" :: "r"(s), "l"(g));
}
#define CP_COMMIT() asm volatile("cp.async.commit_group;" ::: "memory")
#define CP_WAIT(n)  asm volatile("cp.async.wait_group %0;" :: "n"(n) : "memory")

// ---------------- bf16x3-split MMA GEMM ----------------
// C = A * (TB ? B^T : B); A = Ah+Al, B = Bh+Bl; 3 MMAs: AhBh + AlBh + AhBl.
// CTA 128 x BN x 32, 8 warps; 4 smem buffers, 3 in-flight cp.async groups, 1 sync/iter.
template<int BN, bool TB, bool SPLIT>
__global__ __launch_bounds__(256, 1)
void mma_gemm(const bf16* __restrict__ Ah, const bf16* __restrict__ Al,
              const bf16* __restrict__ Bh, const bf16* __restrict__ Bl,
              float* __restrict__ Cf, bf16* __restrict__ Ch, bf16* __restrict__ Cl,
              int Kd, int lda, int ldb, int ldc,
              long long aSb, long long aSh,
              long long bSb, long long bSh,
              long long cSb, long long cSh, int numH)
{
    constexpr int BM    = 128;
    constexpr int BK    = 32;
    constexpr int NF    = BN / 32;
    constexpr int AST   = BK + 8;                 // 40
    constexpr int ATILE = BM * AST;               // 5120
    constexpr int BROWS = TB ? BN : BK;
    constexpr int BST   = TB ? (BK + 8) : (BN + 8);
    constexpr int BTILE = BROWS * BST;
    constexpr int BUFE  = 2 * ATILE + 2 * BTILE;  // elems per buffer
    constexpr int NP4   = BN / 4;
    constexpr int NCHB  = TB ? (BN * 4) : (32 * (BN / 8));  // 16B chunks per B array

    extern __shared__ bf16 sm[];

    const int z  = blockIdx.z;
    const int bb = z / numH;
    const int hh = z - bb * numH;
    const int m0 = blockIdx.y * BM;
    const int n0 = blockIdx.x * BN;
    Ah += bb * aSb + hh * aSh + (long long)m0 * lda;
    Al += bb * aSb + hh * aSh + (long long)m0 * lda;
    Bh += bb * bSb + hh * bSh;
    Bl += bb * bSb + hh * bSh;

    const int tid  = threadIdx.x;
    const int lane = tid & 31;
    const int w    = tid >> 5;
    const int wm   = w & 1;
    const int wn   = w >> 1;

    const uint32_t smb = smem_u32(sm);

    const uint32_t aFrag = (uint32_t)(((wm * 64 + (lane & 15)) * AST + ((lane >> 4) << 3)) * 2);
    uint32_t bFrag;
    if (TB)
        bFrag = (uint32_t)(((wn * NP4 + (lane & 7) + ((lane >> 4) << 3)) * BST
                            + (((lane >> 3) & 1) << 3)) * 2);
    else
        bFrag = (uint32_t)((((lane & 7) + (((lane >> 3) & 1) << 3)) * BST
                            + wn * NP4 + ((lane >> 4) << 3)) * 2);

    float acc[4][NF][4];
    #pragma unroll
    for (int i = 0; i < 4; i++)
        #pragma unroll
        for (int j = 0; j < NF; j++)
            #pragma unroll
            for (int q = 0; q < 4; q++) acc[i][j][q] = 0.f;

    auto issueLoads = [&](int it) {
        const int k0 = it * BK;
        const uint32_t base = smb + (uint32_t)((it & 3) * BUFE * 2);
        #pragma unroll
        for (int r = 0; r < 2; r++) {
            int c   = tid + r * 256;
            int row = c >> 2;
            int ch  = c & 3;
            uint32_t so = base + (uint32_t)((row * AST + ch * 8) * 2);
            const long long go = (long long)row * lda + k0 + ch * 8;
            cpa16(so,                          Ah + go);
            cpa16(so + (uint32_t)(ATILE * 2),  Al + go);
        }
        const uint32_t bBase = base + (uint32_t)(2 * ATILE * 2);
        #pragma unroll
        for (int r = 0; r < NCHB / 256; r++) {
            int c = tid + r * 256;
            int row, ch;
            long long go;
            if (TB) {
                row = c >> 2; ch = c & 3;
                go = (long long)(n0 + row) * ldb + k0 + ch * 8;
            } else {
                row = c / (BN / 8); ch = c % (BN / 8);
                go = (long long)(k0 + row) * ldb + n0 + ch * 8;
            }
            uint32_t so = bBase + (uint32_t)((row * BST + ch * 8) * 2);
            cpa16(so,                          Bh + go);
            cpa16(so + (uint32_t)(BTILE * 2),  Bl + go);
        }
    };

    auto compute = [&](int it) {
        const uint32_t base = smb + (uint32_t)((it & 3) * BUFE * 2);
        const uint32_t aB = base;
        const uint32_t bB = base + (uint32_t)(2 * ATILE * 2);
        #pragma unroll
        for (int ks = 0; ks < 2; ks++) {
            uint32_t ah[4][4], al[4][4];
            #pragma unroll
            for (int i = 0; i < 4; i++) {
                uint32_t ad = aB + aFrag + (uint32_t)((ks * 16) * 2 + i * (16 * AST * 2));
                ldsm4(ad, ah[i]);
                ldsm4(ad + (uint32_t)(ATILE * 2), al[i]);
            }
            uint32_t bh[NF][2], bl[NF][2];
            #pragma unroll
            for (int jj = 0; jj < NF / 2; jj++) {
                uint32_t bd;
                if (TB) {
                    bd = bB + bFrag + (uint32_t)((ks * 16) * 2 + jj * (16 * BST * 2));
                    ldsm4(bd, &bh[2 * jj][0]);
                    ldsm4(bd + (uint32_t)(BTILE * 2), &bl[2 * jj][0]);
                } else {
                    bd = bB + bFrag + (uint32_t)((ks * 16) * BST * 2 + jj * (16 * 2));
                    ldsm4t(bd, &bh[2 * jj][0]);
                    ldsm4t(bd + (uint32_t)(BTILE * 2), &bl[2 * jj][0]);
                }
            }
            #pragma unroll
            for (int i = 0; i < 4; i++)
                #pragma unroll
                for (int j = 0; j < NF; j++) {
                    mma_bf16(acc[i][j], ah[i], bh[j]);
                    mma_bf16(acc[i][j], al[i], bh[j]);
                    mma_bf16(acc[i][j], ah[i], bl[j]);
                }
        }
    };

    const int nIter = Kd / BK;
    // prologue: 2 stages ahead
    #pragma unroll
    for (int p = 0; p < 2; p++) {
        if (p < nIter) issueLoads(p);
        CP_COMMIT();
    }
    for (int it = 0; it < nIter; ++it) {
        const int pre = it + 2;
        if (pre < nIter) issueLoads(pre);
        CP_COMMIT();
        CP_WAIT(2);
        __syncthreads();
        compute(it);
    }

    // ---- epilogue ----
    const long long cOff = bb * cSb + hh * cSh;
    #pragma unroll
    for (int i = 0; i < 4; i++) {
        const int row = m0 + wm * 64 + i * 16 + (lane >> 2);
        #pragma unroll
        for (int j = 0; j < NF; j++) {
            const int col = n0 + wn * NP4 + j * 8 + (lane & 3) * 2;
            const long long o0 = cOff + (long long)row * ldc + col;
            const long long o1 = cOff + (long long)(row + 8) * ldc + col;
            if (SPLIT) {
                *(uint32_t*)&Ch[o0] = pack_hi(acc[i][j][0], acc[i][j][1]);
                *(uint32_t*)&Cl[o0] = pack_lo(acc[i][j][0], acc[i][j][1]);
                *(uint32_t*)&Ch[o1] = pack_hi(acc[i][j][2], acc[i][j][3]);
                *(uint32_t*)&Cl[o1] = pack_lo(acc[i][j][2], acc[i][j][3]);
            } else {
                *(float2*)&Cf[o0] = make_float2(acc[i][j][0], acc[i][j][1]);
                *(float2*)&Cf[o1] = make_float2(acc[i][j][2], acc[i][j][3]);
            }
        }
    }
}

// ---------------- fused fp32 -> hi/lo bf16 split of all 7 inputs ----------------
__device__ __forceinline__ void split4(const float4* __restrict__ in,
                                       uint32_t* __restrict__ hi, uint32_t* __restrict__ lo, int i) {
    float4 v = in[i];
    hi[2 * i]     = pack_hi(v.x, v.y);
    hi[2 * i + 1] = pack_hi(v.z, v.w);
    lo[2 * i]     = pack_lo(v.x, v.y);
    lo[2 * i + 1] = pack_lo(v.z, v.w);
}

// segment sizes in float4 units
#define SZ4_HID   (BB * SS * DIMQ / 4)
#define SZ4_WQ    (HH * KH * DIMQ / 4)
#define SZ4_WKCQ  (HH * KH * DCQ / 4)
#define SZ4_WKCKV (HH * KH * DC / 4)
#define SZ4_WQR   (HH * DCQ * RR / 4)
#define SZ4_WKR   (HH * DC * RR / 4)
#define SZ4_WO    (DIMQ * HH * KH / 4)
#define OFF0 0
#define OFF1 (OFF0 + SZ4_HID)
#define OFF2 (OFF1 + SZ4_WQ)
#define OFF3 (OFF2 + SZ4_WKCQ)
#define OFF4 (OFF3 + SZ4_WKCKV)
#define OFF5 (OFF4 + SZ4_WQR)
#define OFF6 (OFF5 + SZ4_WKR)
#define OFF7 (OFF6 + SZ4_WO)

__global__ void fused_split_kernel(
    const float4* __restrict__ hid, const float4* __restrict__ wq,
    const float4* __restrict__ wkcq, const float4* __restrict__ wkckv,
    const float4* __restrict__ wqr, const float4* __restrict__ wkr,
    const float4* __restrict__ wo,
    uint32_t* __restrict__ hidh, uint32_t* __restrict__ hidl,
    uint32_t* __restrict__ wqh,  uint32_t* __restrict__ wql,
    uint32_t* __restrict__ wkcqh, uint32_t* __restrict__ wkcql,
    uint32_t* __restrict__ wkckvh, uint32_t* __restrict__ wkckvl,
    uint32_t* __restrict__ wqrh, uint32_t* __restrict__ wqrl,
    uint32_t* __restrict__ wkrh, uint32_t* __restrict__ wkrl,
    uint32_t* __restrict__ woh,  uint32_t* __restrict__ wol)
{
    int i = blockIdx.x * blockDim.x + threadIdx.x;
    if (i < OFF1)      split4(hid,   hidh,   hidl,   i - OFF0);
    else if (i < OFF2) split4(wq,    wqh,    wql,    i - OFF1);
    else if (i < OFF3) split4(wkcq,  wkcqh,  wkcql,  i - OFF2);
    else if (i < OFF4) split4(wkckv, wkckvh, wkckvl, i - OFF3);
    else if (i < OFF5) split4(wqr,   wqrh,   wqrl,   i - OFF4);
    else if (i < OFF6) split4(wkr,   wkrh,   wkrl,   i - OFF5);
    else if (i < OFF7) split4(wo,    woh,    wol,    i - OFF6);
}

// ---------------- RoPE fused with split ----------------
__global__ void rope_split_kernel(const float* __restrict__ in,
                                  uint32_t* __restrict__ oh, uint32_t* __restrict__ ol,
                                  long long total, int dim, int half,
                                  int posDiv, int posMod)
{
    long long t = (long long)blockIdx.x * blockDim.x + threadIdx.x;
    if (t >= total) return;
    const int q  = half >> 1;
    const int j  = (int)(t % q) * 2;
    const long long r = t / q;
    const int pos = (int)((r / posDiv) % posMod);

    const float* p = in + r * (long long)dim;
    float x1a = p[j],        x1b = p[j + 1];
    float x2a = p[j + half], x2b = p[j + half + 1];

    const float LOG2_1E4 = 13.28771238f;
    float inv_dim = 1.0f / (float)dim;
    float e1 = exp2f(-LOG2_1E4 * (float)j          * inv_dim);
    float e2 = exp2f(-LOG2_1E4 * (float)(j + half) * inv_dim);
    float s1, c1, s2, c2;
    sincosf((float)pos * e1, &s1, &c1);
    sincosf((float)pos * e2, &s2, &c2);

    float oa = x1a * c1 - x2a * s1, ob = x1b * c1 - x2b * s1;
    float pa = x2a * c2 + x1a * s2, pb = x2b * c2 + x1b * s2;

    long long b0 = (r * dim + j) >> 1;
    long long b1 = (r * dim + j + half) >> 1;
    oh[b0] = pack_hi(oa, ob);  ol[b0] = pack_lo(oa, ob);
    oh[b1] = pack_hi(pa, pb);  ol[b1] = pack_lo(pa, pb);
}

// ---------------- softmax (len 1024) fused with split ----------------
__global__ void softmax_kernel(const float* __restrict__ x,
                               uint32_t* __restrict__ oh, uint32_t* __restrict__ ol)
{
    const float4* p = (const float4*)(x + (long long)blockIdx.x * 1024);
    int tid  = threadIdx.x;
    int w    = tid >> 5;
    int lane = tid & 31;
    __shared__ float sha[8], shb[8];

    float4 v = p[tid];
    float m = fmaxf(fmaxf(v.x, v.y), fmaxf(v.z, v.w));
    #pragma unroll
    for (int o = 16; o > 0; o >>= 1) m = fmaxf(m, __shfl_xor_sync(0xffffffffu, m, o));
    if (lane == 0) sha[w] = m;
    __syncthreads();
    if (tid == 0) {
        float mm = sha[0];
        #pragma unroll
        for (int i = 1; i < 8; i++) mm = fmaxf(mm, sha[i]);
        sha[0] = mm;
    }
    __syncthreads();
    m = sha[0];

    v.x = __expf(v.x - m);
    v.y = __expf(v.y - m);
    v.z = __expf(v.z - m);
    v.w = __expf(v.w - m);
    float s = v.x + v.y + v.z + v.w;
    #pragma unroll
    for (int o = 16; o > 0; o >>= 1) s += __shfl_xor_sync(0xffffffffu, s, o);
    if (lane == 0) shb[w] = s;
    __syncthreads();
    if (tid == 0) {
        float ss = 0.f;
        #pragma unroll
        for (int i = 0; i < 8; i++) ss += shb[i];
        shb[0] = ss;
    }
    __syncthreads();
    float inv = 1.f / shb[0];
    v.x *= inv; v.y *= inv; v.z *= inv; v.w *= inv;

    long long base = ((long long)blockIdx.x * 1024 + tid * 4) >> 1;
    oh[base]     = pack_hi(v.x, v.y);
    oh[base + 1] = pack_hi(v.z, v.w);
    ol[base]     = pack_lo(v.x, v.y);
    ol[base + 1] = pack_lo(v.z, v.w);
}

// ---------------- launch ----------------
static inline void set_smem(const void* fn, int bytes) {
    cudaFuncSetAttribute(fn, cudaFuncAttributeMaxDynamicSharedMemorySize, bytes);
}

#define GETSYM(var, sym) cudaGetSymbolAddress((void**)&var, sym)

extern "C" void kernel_launch(void* const* d_in, const int* in_sizes, int n_in,
                              void* d_out, int out_size)
{
    const float* hidden  = (const float*)d_in[0];
    const float* kv_c    = (const float*)d_in[1];
    const float* Wq      = (const float*)d_in[2];
    const float* w_kc_q  = (const float*)d_in[3];
    const float* w_kc_kv = (const float*)d_in[4];
    const float* W_qr    = (const float*)d_in[5];
    const float* W_kr    = (const float*)d_in[6];
    const float* Wo      = (const float*)d_in[7];
    float* out = (float*)d_out;

    bf16 *hidh, *hidl, *wqh, *wql, *wkcqh, *wkcql, *wkckvh, *wkckvl;
    bf16 *wqrh, *wqrl, *wkrh, *wkrl, *woh, *wol;
    bf16 *qhkh, *qhkl, *qbh, *qbl, *kvrh, *kvrl, *qrh, *qrl, *krh, *krl;
    bf16 *ath, *atl, *vh, *vl, *ctxh, *ctxl;
    float *qbigf, *scf;

    GETSYM(hidh, s_hid_h);     GETSYM(hidl, s_hid_l);
    GETSYM(wqh, s_wq_h);       GETSYM(wql, s_wq_l);
    GETSYM(wkcqh, s_wkcq_h);   GETSYM(wkcql, s_wkcq_l);
    GETSYM(wkckvh, s_wkckv_h); GETSYM(wkckvl, s_wkckv_l);
    GETSYM(wqrh, s_wqr_h);     GETSYM(wqrl, s_wqr_l);
    GETSYM(wkrh, s_wkr_h);     GETSYM(wkrl, s_wkr_l);
    GETSYM(woh, s_wo_h);       GETSYM(wol, s_wo_l);
    GETSYM(qhkh, s_qhk_h);     GETSYM(qhkl, s_qhk_l);
    GETSYM(qbh, s_qbig_h);     GETSYM(qbl, s_qbig_l);
    GETSYM(kvrh, s_kvr_h);     GETSYM(kvrl, s_kvr_l);
    GETSYM(qrh, s_qr_h);       GETSYM(qrl, s_qr_l);
    GETSYM(krh, s_kr_h);       GETSYM(krl, s_kr_l);
    GETSYM(ath, s_at_h);       GETSYM(atl, s_at_l);
    GETSYM(vh, s_v_h);         GETSYM(vl, s_v_l);
    GETSYM(ctxh, s_ctx_h);     GETSYM(ctxl, s_ctx_l);
    GETSYM(qbigf, g_qbig);     GETSYM(scf, g_sc);

    const int MS = BB * SS;
    // dynamic smem: 4 buffers x (2*A + 2*B) bf16 tiles
    const int SM_T128 = 163840;
    const int SM_F128 = 151552;
    const int SM_F64  = 118784;

    set_smem((const void*)mma_gemm<128, true,  true>,  SM_T128);
    set_smem((const void*)mma_gemm<128, true,  false>, SM_T128);
    set_smem((const void*)mma_gemm<128, false, true>,  SM_F128);
    set_smem((const void*)mma_gemm<128, false, false>, SM_F128);
    set_smem((const void*)mma_gemm<64,  false, true>,  SM_F64);

    // [0] fused operand split
    fused_split_kernel<<<OFF7 / 256, 256>>>(
        (const float4*)hidden, (const float4*)Wq, (const float4*)w_kc_q,
        (const float4*)w_kc_kv, (const float4*)W_qr, (const float4*)W_kr,
        (const float4*)Wo,
        (uint32_t*)hidh, (uint32_t*)hidl, (uint32_t*)wqh, (uint32_t*)wql,
        (uint32_t*)wkcqh, (uint32_t*)wkcql, (uint32_t*)wkckvh, (uint32_t*)wkckvl,
        (uint32_t*)wqrh, (uint32_t*)wqrl, (uint32_t*)wkrh, (uint32_t*)wkrl,
        (uint32_t*)woh, (uint32_t*)wol);

    // [1] q_hk = hidden @ Wq^T  -> split out
    mma_gemm<128, true, true><<<dim3(DIMQ/128, MS/128, 1), 256, SM_T128>>>(
        hidh, hidl, wqh, wql, nullptr, qhkh, qhkl,
        DIMQ, DIMQ, DIMQ, HH*KH,
        0, 0, 0, 0, 0, 0, 1);

    // [2] q_big = q_hk[h-slice] @ w_kc_q[h]  -> fp32 (pre-RoPE)
    mma_gemm<128, false, false><<<dim3(DCQ/128, MS/128, HH), 256, SM_F128>>>(
        qhkh, qhkl, wkcqh, wkcql, qbigf, nullptr, nullptr,
        KH, HH*KH, DCQ, HH*DCQ,
        0, KH,
        0, (long long)KH*DCQ,
        0, DCQ,
        HH);

    // [3] RoPE+split q_big
    {
        long long total = (long long)BB * SS * HH * (DCQ / 4);
        rope_split_kernel<<<(unsigned)((total + 255) / 256), 256>>>(
            qbigf, (uint32_t*)qbh, (uint32_t*)qbl, total, DCQ, DCQ/2, HH, SS);
    }
    // [4] RoPE+split kv_c -> kvr
    {
        long long total = (long long)BB * LL * (DC / 4);
        rope_split_kernel<<<(unsigned)((total + 255) / 256), 256>>>(
            kv_c, (uint32_t*)kvrh, (uint32_t*)kvrl, total, DC, DC/2, 1, LL);
    }

    // [5] V[b,h] = kvr[b] @ w_kc_kv[h]^T  [L x KH], K=DC  -> split out
    mma_gemm<128, true, true><<<dim3(1, LL/128, BB*HH), 256, SM_T128>>>(
        kvrh, kvrl, wkckvh, wkckvl, nullptr, vh, vl,
        DC, DC, DC, KH,
        (long long)LL*DC, 0,
        0, (long long)KH*DC,
        (long long)HH*LL*KH, (long long)LL*KH,
        HH);

    // [6] q_r = q_big[b,:,h,:] @ W_qr[h]  -> split out
    mma_gemm<64, false, true><<<dim3(1, SS/128, BB*HH), 256, SM_F64>>>(
        qbh, qbl, wqrh, wqrl, nullptr, qrh, qrl,
        DCQ, HH*DCQ, RR, RR,
        (long long)SS*HH*DCQ, DCQ,
        0, (long long)DCQ*RR,
        (long long)HH*SS*RR, (long long)SS*RR,
        HH);

    // [7] k_r = kvr[b] @ W_kr[h]  -> split out
    mma_gemm<64, false, true><<<dim3(1, LL/128, BB*HH), 256, SM_F64>>>(
        kvrh, kvrl, wkrh, wkrl, nullptr, krh, krl,
        DC, DC, RR, RR,
        (long long)LL*DC, 0,
        0, (long long)DC*RR,
        (long long)HH*LL*RR, (long long)LL*RR,
        HH);

    // [8] scores = q_r @ k_r^T  -> fp32 (pre-softmax)
    mma_gemm<128, true, false><<<dim3(LL/128, SS/128, BB*HH), 256, SM_T128>>>(
        qrh, qrl, krh, krl, scf, nullptr, nullptr,
        RR, RR, RR, LL,
        (long long)HH*SS*RR, (long long)SS*RR,
        (long long)HH*LL*RR, (long long)LL*RR,
        (long long)HH*SS*LL, (long long)SS*LL,
        HH);

    // [9] softmax + split
    softmax_kernel<<<BB*HH*SS, 256>>>(scf, (uint32_t*)ath, (uint32_t*)atl);

    // [10] ctx[b,s,h*K:] = attn[b,h] @ V[b,h]   K=L  -> split out
    mma_gemm<128, false, true><<<dim3(1, SS/128, BB*HH), 256, SM_F128>>>(
        ath, atl, vh, vl, nullptr, ctxh, ctxl,
        LL, LL, KH, HH*KH,
        (long long)HH*SS*LL, (long long)SS*LL,
        (long long)HH*LL*KH, (long long)LL*KH,
        (long long)SS*HH*KH, KH,
        HH);

    // [11] out = ctx @ Wo^T  -> fp32 final
    mma_gemm<128, true, false><<<dim3(DIMQ/128, MS/128, 1), 256, SM_T128>>>(
        ctxh, ctxl, woh, wol, out, nullptr, nullptr,
        HH*KH, HH*KH, HH*KH, DIMQ,
        0, 0, 0, 0, 0, 0, 1);
}